// round 1
// baseline (speedup 1.0000x reference)
#include <cuda_runtime.h>
#include <cstdint>

// ---------------------------------------------------------------------------
// QHashSoftmax: LUT-based fixed-point softmax.
//
// Exact-integer reformulation of the reference:
//   idx = clamp(rne(x*16), -128, 127) & 255          (8-bit code)
//   k[idx] = clip(rint(exp(signed(idx)/16 * scale)*128), -128, 127)  (>= 0)
//   S = sum of k over the 1024-element row           (exact integer)
//   t = (k != 0) ? min(S / k, 1023) : 1023           (exact integer division)
//   out = min(rint(128/t), 127) / 128                (t==0 -> inf -> 127)
//
// All per-element math is exact; only the 256-entry exp table involves a
// transcendental, computed once in double precision by a setup kernel.
// ---------------------------------------------------------------------------

__device__ int g_exp_k[256];

// One block, 256 threads. Builds the quantized exp table from the runtime scale.
__global__ void qhs_setup_kernel(const float* __restrict__ scale_ptr) {
    int i = threadIdx.x;
    float scale = *scale_ptr;
    int sv = (i >= 128) ? (i - 256) : i;          // two's-complement decode
    // reference: signed * (1/2^4) * scale, all fp32, left-to-right
    float val = (float)sv * 0.0625f * scale;
    double e = exp((double)val);                   // high-precision exp
    double r = rint(e * 128.0);                    // round half to even
    if (r > 127.0)  r = 127.0;
    if (r < -128.0) r = -128.0;
    g_exp_k[i] = (int)r;
}

// One block per row of 1024 elements. 256 threads x float4.
__global__ __launch_bounds__(256) void qhs_main_kernel(
    const float4* __restrict__ x, float4* __restrict__ out)
{
    __shared__ int   sk[256];      // exp table (integer codes, k = e*128)
    __shared__ float orow[256];    // per-row output table indexed by idx
    __shared__ int   sS;           // row sum S (integer, exact)

    const int tid = threadIdx.x;

    sk[tid] = g_exp_k[tid];        // L2-resident broadcast load
    if (tid == 0) sS = 0;
    __syncthreads();

    const long long base = (long long)blockIdx.x * 256 + tid;
    float4 v = x[base];

    // idx = clamp(round-half-even(x*16), -128, 127) & 255
    int i0 = (max(-128, min(127, __float2int_rn(v.x * 16.0f)))) & 255;
    int i1 = (max(-128, min(127, __float2int_rn(v.y * 16.0f)))) & 255;
    int i2 = (max(-128, min(127, __float2int_rn(v.z * 16.0f)))) & 255;
    int i3 = (max(-128, min(127, __float2int_rn(v.w * 16.0f)))) & 255;

    int s = sk[i0] + sk[i1] + sk[i2] + sk[i3];

    // exact integer reduction: warp REDUX then one smem atomic per warp
    s = __reduce_add_sync(0xFFFFFFFFu, s);
    if ((tid & 31) == 0) atomicAdd(&sS, s);
    __syncthreads();

    const int S = sS;

    // Build this row's 256-entry output table: one integer division per thread.
    {
        int k = sk[tid];
        int t = (k != 0) ? min(S / k, 1023) : 1023;
        // div table: clip(rint(128/t), -128, 127)/128 ; t==0 -> inf -> 127
        float f = fminf(rintf(128.0f / (float)t), 127.0f) * 0.0078125f;
        orow[tid] = f;
    }
    __syncthreads();

    float4 o;
    o.x = orow[i0];
    o.y = orow[i1];
    o.z = orow[i2];
    o.w = orow[i3];
    out[base] = o;
}

extern "C" void kernel_launch(void* const* d_in, const int* in_sizes, int n_in,
                              void* d_out, int out_size) {
    const float* x     = (const float*)d_in[0];   // [4,12,1024,1024] fp32
    const float* scale = (const float*)d_in[1];   // scalar fp32

    const int n_elems = in_sizes[0];
    const int n_rows  = n_elems >> 10;            // last axis = 1024

    qhs_setup_kernel<<<1, 256>>>(scale);
    qhs_main_kernel<<<n_rows, 256>>>((const float4*)x, (float4*)d_out);
}

// round 2
// speedup vs baseline: 1.3427x; 1.3427x over previous
#include <cuda_runtime.h>

// ---------------------------------------------------------------------------
// QHashSoftmax: LUT fixed-point softmax, exact-integer reformulation.
//   idx = clamp(rne(x*16), -128, 127) & 255
//   k[idx] = clip(rint(exp(signed(idx)/16 * scale)*128), 0, 127)   (u8)
//   S = sum(k) over 1024-element row  (exact integer, < 2^18)
//   t = min(floor(S/k), 1023)  (k=0 -> 1023)   [fp32 div+floor is exact here]
//   out = min(rint(128/t), 127) / 128          (t=0 -> inf -> 127)
//
// Key layout facts:
//  - exp table as u8[256] = 64 smem words -> gather conflict degree <= 2
//  - out table indexed by k: u8[128] = 32 smem words, one per bank ->
//    gather is CONFLICT-FREE (same-word accesses broadcast)
//  - 4 rows per block; all loads issued up front (MLP=4); 3 barriers / 4 rows
// ---------------------------------------------------------------------------

__device__ unsigned char g_exp_u8[256];

__global__ void qhs_setup_kernel(const float* __restrict__ scale_ptr) {
    int i = threadIdx.x;
    float scale = *scale_ptr;
    int sv = (i >= 128) ? (i - 256) : i;            // two's-complement decode
    float val = (float)sv * 0.0625f * scale;        // fp32, matches reference
    double e = exp((double)val);                    // high-precision exp
    double r = rint(e * 128.0);                     // round half to even
    if (r > 127.0) r = 127.0;
    if (r < 0.0)   r = 0.0;                         // exp>0, safety only
    g_exp_u8[i] = (unsigned char)(int)r;
}

#define ROWS_PER_BLOCK 4

__global__ __launch_bounds__(256) void qhs_main_kernel(
    const float4* __restrict__ x, float4* __restrict__ out)
{
    __shared__ unsigned char sk8[256];                      // exp codes (u8)
    __shared__ unsigned char ocode[ROWS_PER_BLOCK][128];    // out codes by k
    __shared__ int sS[ROWS_PER_BLOCK];                      // row sums

    const int tid = threadIdx.x;

    sk8[tid] = g_exp_u8[tid];
    if (tid < ROWS_PER_BLOCK) sS[tid] = 0;

    // Front-load all 4 rows: 4 independent DRAM requests in flight.
    const long long base = (long long)blockIdx.x * (ROWS_PER_BLOCK * 256) + tid;
    float4 v0 = x[base];
    float4 v1 = x[base + 256];
    float4 v2 = x[base + 512];
    float4 v3 = x[base + 768];

    __syncthreads();   // sk8 + sS ready

    // ---- Phase 1: codes + gather k + row sums (all rows, one barrier) ----
    int k[ROWS_PER_BLOCK][4];

#define QHS_IDX(f) \
    ((__float2int_rn(fminf(fmaxf((f) * 16.0f, -128.0f), 127.0f))) & 255)

#define QHS_ROW(r, v)  do {                                            \
        int i0 = QHS_IDX(v.x), i1 = QHS_IDX(v.y);                      \
        int i2 = QHS_IDX(v.z), i3 = QHS_IDX(v.w);                      \
        k[r][0] = sk8[i0]; k[r][1] = sk8[i1];                          \
        k[r][2] = sk8[i2]; k[r][3] = sk8[i3];                          \
        int s = k[r][0] + k[r][1] + k[r][2] + k[r][3];                 \
        s = __reduce_add_sync(0xFFFFFFFFu, s);                         \
        if ((tid & 31) == 0) atomicAdd(&sS[r], s);                     \
    } while (0)

    QHS_ROW(0, v0);
    QHS_ROW(1, v1);
    QHS_ROW(2, v2);
    QHS_ROW(3, v3);

    __syncthreads();   // all sums complete

    // ---- Phase 2: build per-row output-code tables (indexed by k) --------
    // 4 rows x 128 entries = 512; each thread builds 2.
#pragma unroll
    for (int e = tid; e < ROWS_PER_BLOCK * 128; e += 256) {
        int row = e >> 7;
        int kk  = e & 127;
        float Sf = (float)sS[row];                       // exact (< 2^18)
        // floor(S/k): IEEE div then floor — exact (err 0.0078/k < 1/k gap).
        // kk==0 -> +inf -> clipped to 1023 (matches reference e==0 branch).
        float t = fminf(floorf(__fdiv_rn(Sf, (float)kk)), 1023.0f);
        // t==0 -> +inf -> clipped to 127 (matches 1/0 saturation).
        float code = fminf(rintf(__fdiv_rn(128.0f, t)), 127.0f);
        ocode[row][kk] = (unsigned char)(int)code;
    }

    __syncthreads();   // tables ready

    // ---- Phase 3: conflict-free byte gathers + stores --------------------
#define QHS_OUT(r)  do {                                               \
        float4 o;                                                      \
        o.x = (float)ocode[r][k[r][0]] * 0.0078125f;                   \
        o.y = (float)ocode[r][k[r][1]] * 0.0078125f;                   \
        o.z = (float)ocode[r][k[r][2]] * 0.0078125f;                   \
        o.w = (float)ocode[r][k[r][3]] * 0.0078125f;                   \
        out[base + (r) * 256] = o;                                     \
    } while (0)

    QHS_OUT(0);
    QHS_OUT(1);
    QHS_OUT(2);
    QHS_OUT(3);

#undef QHS_IDX
#undef QHS_ROW
#undef QHS_OUT
}

extern "C" void kernel_launch(void* const* d_in, const int* in_sizes, int n_in,
                              void* d_out, int out_size) {
    const float* x     = (const float*)d_in[0];   // [4,12,1024,1024] fp32
    const float* scale = (const float*)d_in[1];   // scalar fp32

    const int n_elems = in_sizes[0];
    const int n_rows  = n_elems >> 10;                       // rows of 1024
    const int n_blocks = n_rows / ROWS_PER_BLOCK;

    qhs_setup_kernel<<<1, 256>>>(scale);
    qhs_main_kernel<<<n_blocks, 256>>>((const float4*)x, (float4*)d_out);
}